// round 1
// baseline (speedup 1.0000x reference)
#include <cuda_runtime.h>
#include <cstdint>

#define NB 8
#define NPTS 65536
#define NC 256
#define K1 259
#define CO 128
#define NS 1024
#define NSTOT (NB*NS)          // 8192 samples per channel for BN
#define EPSV 1e-5f

// ---------------- scratch (device globals; no allocation allowed) ----------------
__device__ float g_y1[NB*CO*NS];
__device__ float g_y2[NB*CO*NS];
__device__ int   g_sel[NB*NS];
__device__ float g_sums[3][CO];
__device__ float g_sumsq[3][CO];
__device__ float g_scale[3][CO];
__device__ float g_shift[3][CO];
__device__ float g_fmax[NB*CO];
__device__ float g_w1t[K1*CO];      // [c][o]
__device__ float g_w2t[CO*CO];
__device__ float g_w3t[CO*CO];

// ---------------- init: zero accumulators + transpose weights ----------------
__global__ void init_kernel(const float* __restrict__ w1,
                            const float* __restrict__ w2,
                            const float* __restrict__ w3) {
    int t = blockIdx.x * blockDim.x + threadIdx.x;
    int stride = gridDim.x * blockDim.x;
    for (int i = t; i < 3*CO; i += stride) {
        ((float*)g_sums)[i]  = 0.f;
        ((float*)g_sumsq)[i] = 0.f;
    }
    for (int i = t; i < K1*CO; i += stride) {
        int o = i / K1, c = i % K1;
        g_w1t[c*CO + o] = w1[i];
    }
    for (int i = t; i < CO*CO; i += stride) {
        int o = i >> 7, c = i & 127;
        g_w2t[c*CO + o] = w2[i];
        g_w3t[c*CO + o] = w3[i];
    }
}

// ---------------- selection: first NS in-radius indices, ascending ----------------
__global__ void select_kernel(const float* __restrict__ xyz) {
    int b = blockIdx.x;
    const float* x = xyz + (size_t)b * NPTS * 3;
    float cx = x[0], cy = x[1], cz = x[2];

    __shared__ int wsum[32];
    __shared__ int woff[32];
    __shared__ int s_total;

    int tid = threadIdx.x;
    int lane = tid & 31, wid = tid >> 5;
    int base = 0;
    const int ITEMS = 4;
    const int CHUNK = 1024 * ITEMS;   // 4096

    for (int chunk = 0; chunk < NPTS / CHUNK; chunk++) {
        int n0 = chunk * CHUNK + tid * ITEMS;
        int vbits = 0;
        #pragma unroll
        for (int j = 0; j < ITEMS; j++) {
            int n = n0 + j;
            float dx = x[n*3+0] - cx;
            float dy = x[n*3+1] - cy;
            float dz = x[n*3+2] - cz;
            if (dx*dx + dy*dy + dz*dz < 1.0f) vbits |= (1 << j);
        }
        int cnt = __popc(vbits);
        // warp inclusive scan of cnt
        int incl = cnt;
        #pragma unroll
        for (int d = 1; d < 32; d <<= 1) {
            int t2 = __shfl_up_sync(0xFFFFFFFFu, incl, d);
            if (lane >= d) incl += t2;
        }
        if (lane == 31) wsum[wid] = incl;
        __syncthreads();
        if (wid == 0) {
            int v = wsum[lane];
            int wincl = v;
            #pragma unroll
            for (int d = 1; d < 32; d <<= 1) {
                int t2 = __shfl_up_sync(0xFFFFFFFFu, wincl, d);
                if (lane >= d) wincl += t2;
            }
            woff[lane] = wincl - v;
            if (lane == 31) s_total = wincl;
        }
        __syncthreads();
        int tbase = base + woff[wid] + (incl - cnt);
        #pragma unroll
        for (int j = 0; j < ITEMS; j++) {
            if (vbits & (1 << j)) {
                int pos = tbase + __popc(vbits & ((1 << j) - 1));
                if (pos < NS) g_sel[b*NS + pos] = n0 + j;
            }
        }
        base += s_total;
        __syncthreads();
        if (base >= NS) break;
    }
    // pad with index 0 (index 0 is always valid: d2 == 0 < R^2, so order[0]==0)
    for (int p = base + tid; p < NS; p += blockDim.x) g_sel[b*NS + p] = 0;
}

// ---------------- GEMM1: y1 = W1 @ [g_xyz; g_feat] + b1, fused gather ----------------
#define KC 8
__global__ __launch_bounds__(256) void gemm1_kernel(const float* __restrict__ bias,
                                                    const float* __restrict__ xyz,
                                                    const float* __restrict__ feats) {
    int b = blockIdx.y, tile = blockIdx.x;
    __shared__ __align__(16) float Ws[KC][CO];
    __shared__ __align__(16) float Bs[KC][64];
    __shared__ int   idx_s[64];
    __shared__ float ssum[CO];
    __shared__ float ssq[CO];
    __shared__ float ctr[3];

    int tid = threadIdx.x;
    if (tid < 64)  idx_s[tid] = g_sel[b*NS + tile*64 + tid];
    if (tid < 3)   ctr[tid] = xyz[(size_t)b * NPTS * 3 + tid];
    if (tid < CO) { ssum[tid] = 0.f; ssq[tid] = 0.f; }
    __syncthreads();

    int tx = tid & 15, ty = tid >> 4;
    float acc[8][4];
    #pragma unroll
    for (int i = 0; i < 8; i++)
        #pragma unroll
        for (int j = 0; j < 4; j++) acc[i][j] = 0.f;

    const float* frow = feats + (size_t)b * NC * NPTS;

    for (int kk = 0; kk < K1; kk += KC) {
        #pragma unroll
        for (int i = 0; i < 4; i++) {
            int e = tid + i*256;
            int cc = e >> 7, o = e & 127;
            int c = kk + cc;
            Ws[cc][o] = (c < K1) ? g_w1t[c*CO + o] : 0.f;
        }
        #pragma unroll
        for (int i = 0; i < 2; i++) {
            int e = tid + i*256;
            int cc = e >> 6, nn = e & 63;
            int c = kk + cc;
            float v = 0.f;
            if (c < K1) {
                int gidx = idx_s[nn];
                if (c < 3) v = xyz[((size_t)b * NPTS + gidx)*3 + c] - ctr[c];
                else       v = frow[(size_t)(c-3) * NPTS + gidx];
            }
            Bs[cc][nn] = v;
        }
        __syncthreads();
        #pragma unroll
        for (int cc = 0; cc < KC; cc++) {
            float wfrag[8], bfrag[4];
            *(float4*)&wfrag[0] = *(const float4*)&Ws[cc][ty*8];
            *(float4*)&wfrag[4] = *(const float4*)&Ws[cc][ty*8+4];
            *(float4*)&bfrag[0] = *(const float4*)&Bs[cc][tx*4];
            #pragma unroll
            for (int i = 0; i < 8; i++)
                #pragma unroll
                for (int j = 0; j < 4; j++)
                    acc[i][j] = fmaf(wfrag[i], bfrag[j], acc[i][j]);
        }
        __syncthreads();
    }

    #pragma unroll
    for (int i = 0; i < 8; i++) {
        int o = ty*8 + i;
        float bv = bias[o];
        float s = 0.f, q = 0.f;
        #pragma unroll
        for (int j = 0; j < 4; j++) {
            float v = acc[i][j] + bv;
            acc[i][j] = v;
            s += v; q += v*v;
        }
        int ng = tile*64 + tx*4;
        *(float4*)&g_y1[((size_t)(b*CO + o))*NS + ng] = *(float4*)&acc[i][0];
        atomicAdd(&ssum[o], s);
        atomicAdd(&ssq[o],  q);
    }
    __syncthreads();
    if (tid < CO) {
        atomicAdd(&g_sums[0][tid],  ssum[tid]);
        atomicAdd(&g_sumsq[0][tid], ssq[tid]);
    }
}

// ---------------- GEMM 2/3: input BN+ReLU fused into B-tile load ----------------
__global__ __launch_bounds__(256) void gemm_mid_kernel(const float* __restrict__ bias,
                                                       int which /*2 or 3*/) {
    const float* wt  = (which == 2) ? g_w2t : g_w3t;
    const float* Yin = (which == 2) ? g_y1  : g_y2;
    float* Yout      = (which == 2) ? g_y2  : g_y1;
    int Lin          = (which == 2) ? 0 : 1;
    int L            = (which == 2) ? 1 : 2;

    int b = blockIdx.y, tile = blockIdx.x;
    __shared__ __align__(16) float Ws[KC][CO];
    __shared__ __align__(16) float Bs[KC][64];
    __shared__ float scl_s[CO];
    __shared__ float shf_s[CO];
    __shared__ float ssum[CO];
    __shared__ float ssq[CO];

    int tid = threadIdx.x;
    if (tid < CO) {
        scl_s[tid] = g_scale[Lin][tid];
        shf_s[tid] = g_shift[Lin][tid];
        ssum[tid] = 0.f; ssq[tid] = 0.f;
    }
    __syncthreads();

    int tx = tid & 15, ty = tid >> 4;
    float acc[8][4];
    #pragma unroll
    for (int i = 0; i < 8; i++)
        #pragma unroll
        for (int j = 0; j < 4; j++) acc[i][j] = 0.f;

    for (int kk = 0; kk < CO; kk += KC) {
        #pragma unroll
        for (int i = 0; i < 4; i++) {
            int e = tid + i*256;
            int cc = e >> 7, o = e & 127;
            Ws[cc][o] = wt[(kk + cc)*CO + o];
        }
        #pragma unroll
        for (int i = 0; i < 2; i++) {
            int e = tid + i*256;
            int cc = e >> 6, nn = e & 63;
            int c = kk + cc;
            float y = Yin[((size_t)(b*CO + c))*NS + tile*64 + nn];
            Bs[cc][nn] = fmaxf(0.f, scl_s[c]*y + shf_s[c]);
        }
        __syncthreads();
        #pragma unroll
        for (int cc = 0; cc < KC; cc++) {
            float wfrag[8], bfrag[4];
            *(float4*)&wfrag[0] = *(const float4*)&Ws[cc][ty*8];
            *(float4*)&wfrag[4] = *(const float4*)&Ws[cc][ty*8+4];
            *(float4*)&bfrag[0] = *(const float4*)&Bs[cc][tx*4];
            #pragma unroll
            for (int i = 0; i < 8; i++)
                #pragma unroll
                for (int j = 0; j < 4; j++)
                    acc[i][j] = fmaf(wfrag[i], bfrag[j], acc[i][j]);
        }
        __syncthreads();
    }

    #pragma unroll
    for (int i = 0; i < 8; i++) {
        int o = ty*8 + i;
        float bv = bias[o];
        float s = 0.f, q = 0.f;
        #pragma unroll
        for (int j = 0; j < 4; j++) {
            float v = acc[i][j] + bv;
            acc[i][j] = v;
            s += v; q += v*v;
        }
        int ng = tile*64 + tx*4;
        *(float4*)&Yout[((size_t)(b*CO + o))*NS + ng] = *(float4*)&acc[i][0];
        atomicAdd(&ssum[o], s);
        atomicAdd(&ssq[o],  q);
    }
    __syncthreads();
    if (tid < CO) {
        atomicAdd(&g_sums[L][tid],  ssum[tid]);
        atomicAdd(&g_sumsq[L][tid], ssq[tid]);
    }
}

// ---------------- BN finalize ----------------
__global__ void bnfin_kernel(int L, const float* __restrict__ gamma,
                             const float* __restrict__ beta) {
    int o = threadIdx.x;
    float m = g_sums[L][o]  * (1.f / NSTOT);
    float v = g_sumsq[L][o] * (1.f / NSTOT) - m*m;
    float s = gamma[o] * rsqrtf(v + EPSV);
    g_scale[L][o] = s;
    g_shift[L][o] = beta[o] - m*s;
}

// ---------------- max over points with BN3+ReLU applied ----------------
__global__ void max_kernel() {
    int o = blockIdx.x, b = blockIdx.y;
    const float* row = g_y1 + ((size_t)(b*CO + o))*NS;   // y3 lives in g_y1
    float s = g_scale[2][o], sh = g_shift[2][o];
    float m = 0.f;   // relu floor; max_n relu(v) == fmax(0, max_n v)
    for (int n = threadIdx.x; n < NS; n += 128)
        m = fmaxf(m, fmaf(s, row[n], sh));
    #pragma unroll
    for (int d = 16; d; d >>= 1)
        m = fmaxf(m, __shfl_xor_sync(0xFFFFFFFFu, m, d));
    __shared__ float wm[4];
    int lane = threadIdx.x & 31, wid = threadIdx.x >> 5;
    if (lane == 0) wm[wid] = m;
    __syncthreads();
    if (threadIdx.x == 0) {
        m = fmaxf(fmaxf(wm[0], wm[1]), fmaxf(wm[2], wm[3]));
        g_fmax[b*CO + o] = m;
    }
}

// ---------------- FC head (BN over batch axis of 8) ----------------
__global__ void head_kernel(const float* __restrict__ hw1, const float* __restrict__ hb1,
                            const float* __restrict__ hg1, const float* __restrict__ hbe1,
                            const float* __restrict__ hw2, const float* __restrict__ hb2,
                            const float* __restrict__ hg2, const float* __restrict__ hbe2,
                            const float* __restrict__ hw3, const float* __restrict__ hb3,
                            const float* __restrict__ xyz, float* __restrict__ out) {
    __shared__ float sf[NB][CO];
    __shared__ float sh[NB][CO];
    int tid = threadIdx.x;
    for (int e = tid; e < NB*CO; e += CO)
        ((float*)sf)[e] = g_fmax[e];
    __syncthreads();

    int o = tid;
    // layer 1
    {
        float a[NB];
        #pragma unroll
        for (int bb = 0; bb < NB; bb++) a[bb] = hb1[o];
        for (int c = 0; c < CO; c++) {
            float w = hw1[o*CO + c];
            #pragma unroll
            for (int bb = 0; bb < NB; bb++) a[bb] = fmaf(w, sf[bb][c], a[bb]);
        }
        float m = 0.f;
        #pragma unroll
        for (int bb = 0; bb < NB; bb++) m += a[bb];
        m *= (1.f/NB);
        float v = 0.f;
        #pragma unroll
        for (int bb = 0; bb < NB; bb++) { float d = a[bb]-m; v += d*d; }
        v *= (1.f/NB);
        float s = hg1[o] * rsqrtf(v + EPSV);
        float be = hbe1[o];
        #pragma unroll
        for (int bb = 0; bb < NB; bb++)
            sh[bb][o] = fmaxf(0.f, fmaf(s, a[bb]-m, be));
    }
    __syncthreads();
    // layer 2
    {
        float a[NB];
        #pragma unroll
        for (int bb = 0; bb < NB; bb++) a[bb] = hb2[o];
        for (int c = 0; c < CO; c++) {
            float w = hw2[o*CO + c];
            #pragma unroll
            for (int bb = 0; bb < NB; bb++) a[bb] = fmaf(w, sh[bb][c], a[bb]);
        }
        float m = 0.f;
        #pragma unroll
        for (int bb = 0; bb < NB; bb++) m += a[bb];
        m *= (1.f/NB);
        float v = 0.f;
        #pragma unroll
        for (int bb = 0; bb < NB; bb++) { float d = a[bb]-m; v += d*d; }
        v *= (1.f/NB);
        float s = hg2[o] * rsqrtf(v + EPSV);
        float be = hbe2[o];
        #pragma unroll
        for (int bb = 0; bb < NB; bb++)
            sf[bb][o] = fmaxf(0.f, fmaf(s, a[bb]-m, be));
    }
    __syncthreads();
    // output layer: 12 features
    if (o < 12) {
        #pragma unroll 1
        for (int bb = 0; bb < NB; bb++) {
            float a = hb3[o];
            for (int c = 0; c < CO; c++) a = fmaf(hw3[o*CO + c], sf[bb][c], a);
            if (o < 3)       out[bb*3 + o]            = xyz[(size_t)bb*NPTS*3 + o] + a;
            else if (o < 6)  out[24 + bb*3 + (o-3)]   = a;
            else             out[48 + bb*6 + (o-6)]   = a;
        }
    }
}

// ---------------- launch ----------------
extern "C" void kernel_launch(void* const* d_in, const int* in_sizes, int n_in,
                              void* d_out, int out_size) {
    const float* xyz   = (const float*)d_in[0];
    const float* feats = (const float*)d_in[1];
    const float* w1  = (const float*)d_in[2];
    const float* b1  = (const float*)d_in[3];
    const float* g1  = (const float*)d_in[4];
    const float* be1 = (const float*)d_in[5];
    const float* w2  = (const float*)d_in[6];
    const float* b2  = (const float*)d_in[7];
    const float* g2  = (const float*)d_in[8];
    const float* be2 = (const float*)d_in[9];
    const float* w3  = (const float*)d_in[10];
    const float* b3  = (const float*)d_in[11];
    const float* g3  = (const float*)d_in[12];
    const float* be3 = (const float*)d_in[13];
    const float* hw1 = (const float*)d_in[14];
    const float* hb1 = (const float*)d_in[15];
    const float* hg1 = (const float*)d_in[16];
    const float* hbe1= (const float*)d_in[17];
    const float* hw2 = (const float*)d_in[18];
    const float* hb2 = (const float*)d_in[19];
    const float* hg2 = (const float*)d_in[20];
    const float* hbe2= (const float*)d_in[21];
    const float* hw3 = (const float*)d_in[22];
    const float* hb3 = (const float*)d_in[23];
    float* out = (float*)d_out;

    init_kernel<<<132, 256>>>(w1, w2, w3);
    select_kernel<<<NB, 1024>>>(xyz);
    gemm1_kernel<<<dim3(16, NB), 256>>>(b1, xyz, feats);
    bnfin_kernel<<<1, 128>>>(0, g1, be1);
    gemm_mid_kernel<<<dim3(16, NB), 256>>>(b2, 2);
    bnfin_kernel<<<1, 128>>>(1, g2, be2);
    gemm_mid_kernel<<<dim3(16, NB), 256>>>(b3, 3);
    bnfin_kernel<<<1, 128>>>(2, g3, be3);
    max_kernel<<<dim3(CO, NB), 128>>>();
    head_kernel<<<1, 128>>>(hw1, hb1, hg1, hbe1, hw2, hb2, hg2, hbe2, hw3, hb3, xyz, out);
}

// round 3
// speedup vs baseline: 1.5400x; 1.5400x over previous
#include <cuda_runtime.h>
#include <cstdint>

#define NB 8
#define NPTS 65536
#define NC 256
#define K1 259
#define CO 128
#define NS 1024
#define NSTOT (NB*NS)
#define EPSV 1e-5f
#define KC 8

// ---------------- scratch (device globals) ----------------
__device__ float g_y1[NB*CO*NS];
__device__ float g_y2[NB*CO*NS];
__device__ int   g_sel[NB*NS];
__device__ unsigned g_mask[NB][2048];
__device__ float g_sums[3][CO];
__device__ float g_sumsq[3][CO];
__device__ unsigned g_fmaxe[NB*CO];
__device__ float g_w1t[264*CO];     // [c][o], zero-padded to 264
__device__ float g_w2t[CO*CO];
__device__ float g_w3t[CO*CO];

// ordered-float encoding for atomicMax on unsigned
__device__ __forceinline__ unsigned enc_f(float x) {
    unsigned u = __float_as_uint(x);
    return (u & 0x80000000u) ? ~u : (u | 0x80000000u);
}
__device__ __forceinline__ float dec_f(unsigned e) {
    return (e & 0x80000000u) ? __uint_as_float(e ^ 0x80000000u) : __uint_as_float(~e);
}

__device__ __forceinline__ void ffma2(unsigned long long& acc, unsigned long long a, unsigned long long b) {
    asm("fma.rn.f32x2 %0, %1, %2, %0;" : "+l"(acc) : "l"(a), "l"(b));
}
__device__ __forceinline__ unsigned long long pack2(float x) {
    unsigned long long r;
    asm("mov.b64 %0, {%1, %1};" : "=l"(r) : "f"(x));
    return r;
}

// ---------------- init ----------------
__global__ void init_kernel(const float* __restrict__ w1,
                            const float* __restrict__ w2,
                            const float* __restrict__ w3) {
    int t = blockIdx.x * blockDim.x + threadIdx.x;
    int stride = gridDim.x * blockDim.x;
    for (int i = t; i < 3*CO; i += stride) {
        ((float*)g_sums)[i]  = 0.f;
        ((float*)g_sumsq)[i] = 0.f;
    }
    for (int i = t; i < NB*CO; i += stride) g_fmaxe[i] = 0u;
    for (int i = t; i < 264*CO; i += stride) {
        int c = i >> 7, o = i & 127;
        g_w1t[c*CO + o] = (c < K1) ? w1[o*K1 + c] : 0.f;
    }
    for (int i = t; i < CO*CO; i += stride) {
        int o = i >> 7, c = i & 127;
        g_w2t[c*CO + o] = w2[i];
        g_w3t[c*CO + o] = w3[i];
    }
}

// ---------------- selection phase A: bitmask ----------------
__global__ void selA_kernel(const float* __restrict__ xyz) {
    int b = blockIdx.y, chunk = blockIdx.x;          // 32 chunks x 2048 pts
    const float* x = xyz + (size_t)b * NPTS * 3;
    float cx = x[0], cy = x[1], cz = x[2];
    int t = threadIdx.x;                             // 256
    int p0 = chunk*2048 + t*8;
    const float4* xv = (const float4*)(x + (size_t)p0 * 3);
    float4 q0 = xv[0], q1 = xv[1], q2 = xv[2], q3 = xv[3], q4 = xv[4], q5 = xv[5];
    float v[24] = {q0.x,q0.y,q0.z,q0.w, q1.x,q1.y,q1.z,q1.w, q2.x,q2.y,q2.z,q2.w,
                   q3.x,q3.y,q3.z,q3.w, q4.x,q4.y,q4.z,q4.w, q5.x,q5.y,q5.z,q5.w};
    unsigned byte = 0;
    #pragma unroll
    for (int j = 0; j < 8; j++) {
        float dx = v[3*j]-cx, dy = v[3*j+1]-cy, dz = v[3*j+2]-cz;
        if (dx*dx + dy*dy + dz*dz < 1.0f) byte |= (1u << j);
    }
    __shared__ unsigned char nb[256];
    nb[t] = (unsigned char)byte;
    __syncthreads();
    if (t < 64) {
        unsigned w = (unsigned)nb[4*t] | ((unsigned)nb[4*t+1] << 8)
                   | ((unsigned)nb[4*t+2] << 16) | ((unsigned)nb[4*t+3] << 24);
        g_mask[b][chunk*64 + t] = w;
    }
}

// ---------------- selection phase B: scan + compact ----------------
__global__ void selB_kernel() {
    int b = blockIdx.x;
    int t = threadIdx.x;                 // 1024
    int lane = t & 31, wid = t >> 5;
    unsigned w0 = g_mask[b][2*t], w1 = g_mask[b][2*t+1];
    int cnt = __popc(w0) + __popc(w1);
    int incl = cnt;
    #pragma unroll
    for (int d = 1; d < 32; d <<= 1) {
        int v = __shfl_up_sync(0xFFFFFFFFu, incl, d);
        if (lane >= d) incl += v;
    }
    __shared__ int wsum[32], woff[32], s_total;
    if (lane == 31) wsum[wid] = incl;
    __syncthreads();
    if (wid == 0) {
        int v = wsum[lane];
        int wincl = v;
        #pragma unroll
        for (int d = 1; d < 32; d <<= 1) {
            int u = __shfl_up_sync(0xFFFFFFFFu, wincl, d);
            if (lane >= d) wincl += u;
        }
        woff[lane] = wincl - v;
        if (lane == 31) s_total = wincl;
    }
    __syncthreads();
    int pos = woff[wid] + incl - cnt;
    int base_idx = t * 64;
    while (w0) {
        int bit = __ffs(w0) - 1; w0 &= w0 - 1;
        if (pos < NS) g_sel[b*NS + pos] = base_idx + bit;
        pos++;
    }
    while (w1) {
        int bit = __ffs(w1) - 1; w1 &= w1 - 1;
        if (pos < NS) g_sel[b*NS + pos] = base_idx + 32 + bit;
        pos++;
    }
    for (int p = s_total + t; p < NS; p += 1024) g_sel[b*NS + p] = 0;
}

// ---------------- shared GEMM machinery ----------------
__device__ __forceinline__ void mma_step(const float (*Ws)[CO], const float (*Bs)[64],
                                         int ty, int tx, unsigned long long (*acc2)[2]) {
    #pragma unroll
    for (int cc = 0; cc < KC; cc++) {
        float4 wa = *(const float4*)&Ws[cc][ty*8];
        float4 wb = *(const float4*)&Ws[cc][ty*8 + 4];
        union { float4 f4; unsigned long long u2[2]; } bu;
        bu.f4 = *(const float4*)&Bs[cc][tx*4];
        float wf[8] = {wa.x, wa.y, wa.z, wa.w, wb.x, wb.y, wb.z, wb.w};
        #pragma unroll
        for (int i = 0; i < 8; i++) {
            unsigned long long wp = pack2(wf[i]);
            ffma2(acc2[i][0], wp, bu.u2[0]);
            ffma2(acc2[i][1], wp, bu.u2[1]);
        }
    }
}

// ---------------- GEMM1: fused gather, K=264 (padded) ----------------
__global__ __launch_bounds__(256) void gemm1_kernel(const float* __restrict__ bias,
                                                    const float* __restrict__ xyz,
                                                    const float* __restrict__ feats) {
    int b = blockIdx.y, tile = blockIdx.x;
    __shared__ __align__(16) float Ws[2][KC][CO];
    __shared__ __align__(16) float Bs[2][KC][64];
    __shared__ int   idx_s[64];
    __shared__ float ssum[CO], ssq[CO];
    __shared__ float ctr[3];

    int tid = threadIdx.x;
    if (tid < 64)  idx_s[tid] = g_sel[b*NS + tile*64 + tid];
    if (tid < 3)   ctr[tid] = xyz[(size_t)b * NPTS * 3 + tid];
    if (tid < CO) { ssum[tid] = 0.f; ssq[tid] = 0.f; }
    __syncthreads();

    const float* frow = feats + (size_t)b * NC * NPTS;
    int tx = tid & 15, ty = tid >> 4;
    unsigned long long acc2[8][2];
    #pragma unroll
    for (int i = 0; i < 8; i++) { acc2[i][0] = 0ull; acc2[i][1] = 0ull; }

    const int NIT = 33;     // 264 / 8
    float wreg[4], breg[2];

    // stage 0 load
    #pragma unroll
    for (int i = 0; i < 4; i++) {
        int e = tid + i*256; int cc = e >> 7, o = e & 127;
        wreg[i] = g_w1t[cc*CO + o];
    }
    #pragma unroll
    for (int i = 0; i < 2; i++) {
        int e = tid + i*256; int cc = e >> 6, nn = e & 63;
        int gi = idx_s[nn];
        breg[i] = (cc < 3) ? xyz[((size_t)b*NPTS + gi)*3 + cc] - ctr[cc]
                           : frow[(size_t)(cc-3)*NPTS + gi];
    }
    #pragma unroll
    for (int i = 0; i < 4; i++) { int e = tid + i*256; Ws[0][e>>7][e&127] = wreg[i]; }
    #pragma unroll
    for (int i = 0; i < 2; i++) { int e = tid + i*256; Bs[0][e>>6][e&63] = breg[i]; }
    __syncthreads();

    for (int s = 0; s < NIT; s++) {
        int cur = s & 1, nxt = cur ^ 1;
        if (s + 1 < NIT) {
            int kk = (s + 1) * KC;
            #pragma unroll
            for (int i = 0; i < 4; i++) {
                int e = tid + i*256; int cc = e >> 7, o = e & 127;
                wreg[i] = g_w1t[(kk+cc)*CO + o];       // padded to 264, always in-bounds
            }
            #pragma unroll
            for (int i = 0; i < 2; i++) {
                int e = tid + i*256; int cc = e >> 6, nn = e & 63;
                int c = kk + cc;
                float v = 0.f;
                if (c < K1) {
                    int gi = idx_s[nn];
                    v = (c < 3) ? xyz[((size_t)b*NPTS + gi)*3 + c] - ctr[c]
                                : frow[(size_t)(c-3)*NPTS + gi];
                }
                breg[i] = v;
            }
        }
        mma_step(Ws[cur], Bs[cur], ty, tx, acc2);
        __syncthreads();
        if (s + 1 < NIT) {
            #pragma unroll
            for (int i = 0; i < 4; i++) { int e = tid + i*256; Ws[nxt][e>>7][e&127] = wreg[i]; }
            #pragma unroll
            for (int i = 0; i < 2; i++) { int e = tid + i*256; Bs[nxt][e>>6][e&63] = breg[i]; }
            __syncthreads();
        }
    }

    #pragma unroll
    for (int i = 0; i < 8; i++) {
        int o = ty*8 + i;
        float v0, v1, v2, v3;
        asm("mov.b64 {%0,%1}, %2;" : "=f"(v0), "=f"(v1) : "l"(acc2[i][0]));
        asm("mov.b64 {%0,%1}, %2;" : "=f"(v2), "=f"(v3) : "l"(acc2[i][1]));
        float bv = bias[o];
        v0 += bv; v1 += bv; v2 += bv; v3 += bv;
        float s4 = v0+v1+v2+v3;
        float q4 = v0*v0+v1*v1+v2*v2+v3*v3;
        float4 st = {v0, v1, v2, v3};
        *(float4*)&g_y1[((size_t)(b*CO + o))*NS + tile*64 + tx*4] = st;
        atomicAdd(&ssum[o], s4);
        atomicAdd(&ssq[o],  q4);
    }
    __syncthreads();
    if (tid < CO) {
        atomicAdd(&g_sums[0][tid],  ssum[tid]);
        atomicAdd(&g_sumsq[0][tid], ssq[tid]);
    }
}

// ---------------- GEMM 2 / 3 (L=1: y2=W2·bn(y1); L=2: stats+max only) ----------------
template<int L>
__global__ __launch_bounds__(256) void gemm_mid_kernel(const float* __restrict__ bias,
                                                       const float* __restrict__ gin,
                                                       const float* __restrict__ bein) {
    const float* wt  = (L == 1) ? g_w2t : g_w3t;
    const float* Yin = (L == 1) ? g_y1  : g_y2;
    int b = blockIdx.y, tile = blockIdx.x;
    __shared__ __align__(16) float Ws[2][KC][CO];
    __shared__ __align__(16) float Bs[2][KC][64];
    __shared__ float scl_s[CO], shf_s[CO];
    __shared__ float ssum[CO], ssq[CO];
    __shared__ unsigned smax[CO];

    int tid = threadIdx.x;
    if (tid < CO) {
        float m = g_sums[L-1][tid] * (1.f/NSTOT);
        float var = g_sumsq[L-1][tid] * (1.f/NSTOT) - m*m;
        float s = gin[tid] * rsqrtf(var + EPSV);
        scl_s[tid] = s;
        shf_s[tid] = bein[tid] - m*s;
        ssum[tid] = 0.f; ssq[tid] = 0.f; smax[tid] = 0u;
    }
    __syncthreads();

    int tx = tid & 15, ty = tid >> 4;
    unsigned long long acc2[8][2];
    #pragma unroll
    for (int i = 0; i < 8; i++) { acc2[i][0] = 0ull; acc2[i][1] = 0ull; }

    const int NIT = CO / KC;   // 16
    float wreg[4], breg[2];

    #pragma unroll
    for (int i = 0; i < 4; i++) { int e = tid + i*256; wreg[i] = wt[(e>>7)*CO + (e&127)]; }
    #pragma unroll
    for (int i = 0; i < 2; i++) {
        int e = tid + i*256; int cc = e >> 6, nn = e & 63;
        float y = Yin[((size_t)(b*CO + cc))*NS + tile*64 + nn];
        breg[i] = fmaxf(0.f, fmaf(scl_s[cc], y, shf_s[cc]));
    }
    #pragma unroll
    for (int i = 0; i < 4; i++) { int e = tid + i*256; Ws[0][e>>7][e&127] = wreg[i]; }
    #pragma unroll
    for (int i = 0; i < 2; i++) { int e = tid + i*256; Bs[0][e>>6][e&63] = breg[i]; }
    __syncthreads();

    for (int s = 0; s < NIT; s++) {
        int cur = s & 1, nxt = cur ^ 1;
        if (s + 1 < NIT) {
            int kk = (s + 1) * KC;
            #pragma unroll
            for (int i = 0; i < 4; i++) {
                int e = tid + i*256;
                wreg[i] = wt[(kk + (e>>7))*CO + (e&127)];
            }
            #pragma unroll
            for (int i = 0; i < 2; i++) {
                int e = tid + i*256; int cc = kk + (e >> 6), nn = e & 63;
                float y = Yin[((size_t)(b*CO + cc))*NS + tile*64 + nn];
                breg[i] = fmaxf(0.f, fmaf(scl_s[cc], y, shf_s[cc]));
            }
        }
        mma_step(Ws[cur], Bs[cur], ty, tx, acc2);
        __syncthreads();
        if (s + 1 < NIT) {
            #pragma unroll
            for (int i = 0; i < 4; i++) { int e = tid + i*256; Ws[nxt][e>>7][e&127] = wreg[i]; }
            #pragma unroll
            for (int i = 0; i < 2; i++) { int e = tid + i*256; Bs[nxt][e>>6][e&63] = breg[i]; }
            __syncthreads();
        }
    }

    #pragma unroll
    for (int i = 0; i < 8; i++) {
        int o = ty*8 + i;
        float v0, v1, v2, v3;
        asm("mov.b64 {%0,%1}, %2;" : "=f"(v0), "=f"(v1) : "l"(acc2[i][0]));
        asm("mov.b64 {%0,%1}, %2;" : "=f"(v2), "=f"(v3) : "l"(acc2[i][1]));
        float bv = bias[o];
        v0 += bv; v1 += bv; v2 += bv; v3 += bv;
        float s4 = v0+v1+v2+v3;
        float q4 = v0*v0+v1*v1+v2*v2+v3*v3;
        if (L == 1) {
            float4 st = {v0, v1, v2, v3};
            *(float4*)&g_y2[((size_t)(b*CO + o))*NS + tile*64 + tx*4] = st;
        } else {
            float m = fmaxf(fmaxf(v0, v1), fmaxf(v2, v3));
            atomicMax(&smax[o], enc_f(m));
        }
        atomicAdd(&ssum[o], s4);
        atomicAdd(&ssq[o],  q4);
    }
    __syncthreads();
    if (tid < CO) {
        atomicAdd(&g_sums[L][tid],  ssum[tid]);
        atomicAdd(&g_sumsq[L][tid], ssq[tid]);
        if (L == 2) atomicMax(&g_fmaxe[b*CO + tid], smax[tid]);
    }
}

// ---------------- FC head ----------------
__global__ void head_kernel(const float* __restrict__ g3, const float* __restrict__ be3,
                            const float* __restrict__ hw1, const float* __restrict__ hb1,
                            const float* __restrict__ hg1, const float* __restrict__ hbe1,
                            const float* __restrict__ hw2, const float* __restrict__ hb2,
                            const float* __restrict__ hg2, const float* __restrict__ hbe2,
                            const float* __restrict__ hw3, const float* __restrict__ hb3,
                            const float* __restrict__ xyz, float* __restrict__ out) {
    __shared__ float sf[NB][CO];
    __shared__ float sh[NB][CO];
    int o = threadIdx.x;   // 128

    // finalize layer-3 BN + relu on pooled max
    {
        float m = g_sums[2][o] * (1.f/NSTOT);
        float var = g_sumsq[2][o] * (1.f/NSTOT) - m*m;
        float s = g3[o] * rsqrtf(var + EPSV);
        float shf = be3[o] - m*s;
        #pragma unroll
        for (int bb = 0; bb < NB; bb++)
            sf[bb][o] = fmaxf(0.f, fmaf(s, dec_f(g_fmaxe[bb*CO + o]), shf));
    }
    __syncthreads();

    // layer 1
    {
        float a[NB];
        #pragma unroll
        for (int bb = 0; bb < NB; bb++) a[bb] = hb1[o];
        for (int c = 0; c < CO; c++) {
            float w = hw1[o*CO + c];
            #pragma unroll
            for (int bb = 0; bb < NB; bb++) a[bb] = fmaf(w, sf[bb][c], a[bb]);
        }
        float m = 0.f;
        #pragma unroll
        for (int bb = 0; bb < NB; bb++) m += a[bb];
        m *= (1.f/NB);
        float v = 0.f;
        #pragma unroll
        for (int bb = 0; bb < NB; bb++) { float d = a[bb]-m; v += d*d; }
        v *= (1.f/NB);
        float s = hg1[o] * rsqrtf(v + EPSV);
        float be = hbe1[o];
        #pragma unroll
        for (int bb = 0; bb < NB; bb++)
            sh[bb][o] = fmaxf(0.f, fmaf(s, a[bb]-m, be));
    }
    __syncthreads();
    // layer 2
    {
        float a[NB];
        #pragma unroll
        for (int bb = 0; bb < NB; bb++) a[bb] = hb2[o];
        for (int c = 0; c < CO; c++) {
            float w = hw2[o*CO + c];
            #pragma unroll
            for (int bb = 0; bb < NB; bb++) a[bb] = fmaf(w, sh[bb][c], a[bb]);
        }
        float m = 0.f;
        #pragma unroll
        for (int bb = 0; bb < NB; bb++) m += a[bb];
        m *= (1.f/NB);
        float v = 0.f;
        #pragma unroll
        for (int bb = 0; bb < NB; bb++) { float d = a[bb]-m; v += d*d; }
        v *= (1.f/NB);
        float s = hg2[o] * rsqrtf(v + EPSV);
        float be = hbe2[o];
        #pragma unroll
        for (int bb = 0; bb < NB; bb++)
            sf[bb][o] = fmaxf(0.f, fmaf(s, a[bb]-m, be));
    }
    __syncthreads();
    // output layer
    if (o < 12) {
        #pragma unroll 1
        for (int bb = 0; bb < NB; bb++) {
            float a = hb3[o];
            for (int c = 0; c < CO; c++) a = fmaf(hw3[o*CO + c], sf[bb][c], a);
            if (o < 3)       out[bb*3 + o]          = xyz[(size_t)bb*NPTS*3 + o] + a;
            else if (o < 6)  out[24 + bb*3 + (o-3)] = a;
            else             out[48 + bb*6 + (o-6)] = a;
        }
    }
}

// ---------------- launch ----------------
extern "C" void kernel_launch(void* const* d_in, const int* in_sizes, int n_in,
                              void* d_out, int out_size) {
    const float* xyz   = (const float*)d_in[0];
    const float* feats = (const float*)d_in[1];
    const float* w1  = (const float*)d_in[2];
    const float* b1  = (const float*)d_in[3];
    const float* g1  = (const float*)d_in[4];
    const float* be1 = (const float*)d_in[5];
    const float* w2  = (const float*)d_in[6];
    const float* b2  = (const float*)d_in[7];
    const float* g2  = (const float*)d_in[8];
    const float* be2 = (const float*)d_in[9];
    const float* w3  = (const float*)d_in[10];
    const float* b3  = (const float*)d_in[11];
    const float* g3  = (const float*)d_in[12];
    const float* be3 = (const float*)d_in[13];
    const float* hw1 = (const float*)d_in[14];
    const float* hb1 = (const float*)d_in[15];
    const float* hg1 = (const float*)d_in[16];
    const float* hbe1= (const float*)d_in[17];
    const float* hw2 = (const float*)d_in[18];
    const float* hb2 = (const float*)d_in[19];
    const float* hg2 = (const float*)d_in[20];
    const float* hbe2= (const float*)d_in[21];
    const float* hw3 = (const float*)d_in[22];
    const float* hb3 = (const float*)d_in[23];
    float* out = (float*)d_out;

    init_kernel<<<132, 256>>>(w1, w2, w3);
    selA_kernel<<<dim3(32, NB), 256>>>(xyz);
    selB_kernel<<<NB, 1024>>>();
    gemm1_kernel<<<dim3(16, NB), 256>>>(b1, xyz, feats);
    gemm_mid_kernel<1><<<dim3(16, NB), 256>>>(b2, g1, be1);
    gemm_mid_kernel<2><<<dim3(16, NB), 256>>>(b3, g2, be2);
    head_kernel<<<1, 128>>>(g3, be3, hw1, hb1, hg1, hbe1, hw2, hb2, hg2, hbe2, hw3, hb3, xyz, out);
}